// round 3
// baseline (speedup 1.0000x reference)
#include <cuda_runtime.h>
#include <math.h>

#define N_MOL  2048
#define P_PRO  2048
#define HID    64
#define HEADS  16
#define NGRAPH 64
#define NB     256
#define NBLK   16          // one block per head; all co-resident
#define NTHR   1024
#define ROWS_PER_BLK ((N_MOL + P_PRO) / NBLK)   // 256

// ---- scratch (no allocation allowed) ----
__device__ float g_amolT[HEADS][N_MOL];
__device__ float g_aproT[HEADS][P_PRO];
__device__ float g_ys[NGRAPH * HEADS];
__device__ int   g_gen;     // barrier generation (monotone across replays)
__device__ int   g_count;   // barrier arrivals (self-resets)
__device__ int   g_done;    // head blocks finished (self-resets)

struct SmemB {
    float  bufA[P_PRO];      // raw a_pro -> later y_atom
    float  bufB[P_PRO];      // bin-grouped values
    float  bufC[P_PRO];      // bin-grouped exp(values)
    int    bs[N_MOL];        // batch ids
    int    hist[NB];
    int    cnt[NB];
    int    binStart[NB + 1];
    float  prefExp[NB];      // sum exp over bins < k
    float  sufVal[NB + 1];   // sum val over bins >= k
    float  wmn[32], wmx[32];
    int    iwarp[8];
    double dwarpE[8], dwarpV[8];
    float  mnv, mxv;
    int    flag;
};
struct SmemA { float W[2 * HID * HEADS]; };   // 8KB weights
union SmemU { SmemA a; SmemB b; };

__device__ __forceinline__ int bin_of(float v, float mn, float inv) {
    int b = (int)(__fmul_rn(__fsub_rn(v, mn), inv));
    return b < 0 ? 0 : (b > NB - 1 ? NB - 1 : b);
}

__global__ __launch_bounds__(NTHR, 1)
void fused_kernel(const float* __restrict__ mol,
                  const float* __restrict__ pro,
                  const float* __restrict__ Wmu,
                  const float* __restrict__ bmu,
                  const float* __restrict__ W1,
                  const float* __restrict__ b1,
                  const float* __restrict__ W2,
                  const float* __restrict__ b2,
                  const int*   __restrict__ batch32,
                  float* __restrict__ out) {
    __shared__ SmemU sm;
    int tid  = threadIdx.x;
    int lane = tid & 31;
    int wrp  = tid >> 5;

    // ============ Phase A: projections (all 16 blocks, 256 rows each) ============
    for (int i = tid; i < 2 * HID * HEADS; i += NTHR) sm.a.W[i] = Wmu[i];
    __syncthreads();
    {
        int row = blockIdx.x * ROWS_PER_BLK + (tid >> 2);  // 4 lanes per row
        int seg = tid & 3;                                  // 16-float segment
        bool is_mol = (row < N_MOL);
        const float* src = is_mol ? (mol + row * HID + seg * 16)
                                  : (pro + (row - N_MOL) * HID + seg * 16);
        float v[16];
#pragma unroll
        for (int q = 0; q < 4; q++) {
            float4 t4 = *(const float4*)(src + 4 * q);
            v[4*q] = t4.x; v[4*q+1] = t4.y; v[4*q+2] = t4.z; v[4*q+3] = t4.w;
        }
        int wbase = (seg * 16 + (is_mol ? 0 : HID)) * HEADS;
        float acc[HEADS];
#pragma unroll
        for (int hh = 0; hh < HEADS; hh++) acc[hh] = 0.0f;
#pragma unroll
        for (int k = 0; k < 16; k++) {
            float vk = v[k];
#pragma unroll
            for (int hh = 0; hh < HEADS; hh++)
                acc[hh] += vk * sm.a.W[wbase + k * HEADS + hh];
        }
#pragma unroll
        for (int hh = 0; hh < HEADS; hh++) {
            acc[hh] += __shfl_xor_sync(0xffffffffu, acc[hh], 1);
            acc[hh] += __shfl_xor_sync(0xffffffffu, acc[hh], 2);
        }
        int h0 = seg * 4;   // each lane writes 4 heads
#pragma unroll
        for (int j = 0; j < 4; j++) {
            int hh = h0 + j;
            if (is_mol) g_amolT[hh][row] = acc[hh] + bmu[hh];
            else        g_aproT[hh][row - N_MOL] = acc[hh];
        }
    }

    // ============ grid barrier (16 blocks) ============
    __threadfence();
    __syncthreads();
    if (tid == 0) {
        int my = *(volatile int*)&g_gen;
        if (atomicAdd(&g_count, 1) == NBLK - 1) {
            atomicExch(&g_count, 0);
            __threadfence();
            atomicAdd(&g_gen, 1);
        } else {
            while (*(volatile int*)&g_gen == my) {}
        }
        __threadfence();
    }
    __syncthreads();

    // ============ Phase B: per-head pipeline (block h) ============
    int h = blockIdx.x;

    float mn = 1e30f, mx = -1e30f;
    for (int i = tid; i < P_PRO; i += NTHR) {
        float v = g_aproT[h][i];
        sm.b.bufA[i] = v;
        mn = fminf(mn, v); mx = fmaxf(mx, v);
    }
    for (int i = tid; i < N_MOL; i += NTHR) sm.b.bs[i] = batch32[i];
    if (tid < NB) { sm.b.hist[tid] = 0; sm.b.cnt[tid] = 0; }
    if (tid == 0) sm.b.flag = 0;
#pragma unroll
    for (int o = 16; o > 0; o >>= 1) {
        mn = fminf(mn, __shfl_xor_sync(0xffffffffu, mn, o));
        mx = fmaxf(mx, __shfl_xor_sync(0xffffffffu, mx, o));
    }
    if (lane == 0) { sm.b.wmn[wrp] = mn; sm.b.wmx[wrp] = mx; }
    __syncthreads();
    // warp 0 reduces the 32 partials
    if (wrp == 0) {
        float a = sm.b.wmn[lane], b = sm.b.wmx[lane];
#pragma unroll
        for (int o = 16; o > 0; o >>= 1) {
            a = fminf(a, __shfl_xor_sync(0xffffffffu, a, o));
            b = fmaxf(b, __shfl_xor_sync(0xffffffffu, b, o));
        }
        if (lane == 0) { sm.b.mnv = a; sm.b.mxv = b; }
    }
    // int64 detection: sorted int32 stream is monotone; int64 word stream is not
    for (int i = tid; i < N_MOL - 1; i += NTHR)
        if (sm.b.bs[i] > sm.b.bs[i + 1]) sm.b.flag = 1;
    __syncthreads();
    if (sm.b.flag) {
        for (int i = tid; i < N_MOL; i += NTHR) sm.b.bs[i] = batch32[2 * i];
    }
    float mnv = sm.b.mnv;
    float inv = (sm.b.mxv > mnv) ? (float)NB / (sm.b.mxv - mnv) : 0.0f;
    __syncthreads();   // also covers bs reload

    // histogram (2 elements per thread)
    for (int i = tid; i < P_PRO; i += NTHR)
        atomicAdd(&sm.b.hist[bin_of(sm.b.bufA[i], mnv, inv)], 1);
    __syncthreads();

    // exclusive scan of hist -> binStart (warp-shfl hierarchical, 2 barriers)
    {
        int c = (tid < NB) ? sm.b.hist[tid] : 0;
        int s = c;
#pragma unroll
        for (int o = 1; o < 32; o <<= 1) {
            int t = __shfl_up_sync(0xffffffffu, s, o);
            if (lane >= o) s += t;
        }
        if (tid < NB && lane == 31) sm.b.iwarp[wrp] = s;
        __syncthreads();
        if (tid < 8) {
            int p = sm.b.iwarp[tid];
#pragma unroll
            for (int o = 1; o < 8; o <<= 1) {
                int t = __shfl_up_sync(0xffu, p, o);
                if (tid >= o) p += t;
            }
            sm.b.iwarp[tid] = p;
        }
        __syncthreads();
        if (tid < NB) {
            int incl = s + (wrp > 0 ? sm.b.iwarp[wrp - 1] : 0);
            sm.b.binStart[tid + 1] = incl;
            if (tid == 0) sm.b.binStart[0] = 0;
        }
    }
    __syncthreads();

    // scatter into bins (value + exp)
    for (int i = tid; i < P_PRO; i += NTHR) {
        float v = sm.b.bufA[i];
        int b = bin_of(v, mnv, inv);
        int pos = sm.b.binStart[b] + atomicAdd(&sm.b.cnt[b], 1);
        sm.b.bufB[pos] = v;
        sm.b.bufC[pos] = expf(v);
    }
    __syncthreads();

    // per-bin sums + joint double scan (prefExp exclusive, sufVal suffix)
    {
        double se = 0.0, sv = 0.0;
        if (tid < NB) {
            int s0 = sm.b.binStart[tid], e0 = sm.b.binStart[tid + 1];
            float fe = 0.0f, fv = 0.0f;
            for (int i = s0; i < e0; i++) { fe += sm.b.bufC[i]; fv += sm.b.bufB[i]; }
            se = (double)fe; sv = (double)fv;
        }
        double ise = se, isv = sv;
#pragma unroll
        for (int o = 1; o < 32; o <<= 1) {
            double te = __shfl_up_sync(0xffffffffu, ise, o);
            double tv = __shfl_up_sync(0xffffffffu, isv, o);
            if (lane >= o) { ise += te; isv += tv; }
        }
        if (tid < NB && lane == 31) { sm.b.dwarpE[wrp] = ise; sm.b.dwarpV[wrp] = isv; }
        __syncthreads();
        if (tid < 8) {
            double pe = sm.b.dwarpE[tid], pv = sm.b.dwarpV[tid];
#pragma unroll
            for (int o = 1; o < 8; o <<= 1) {
                double te = __shfl_up_sync(0xffu, pe, o);
                double tv = __shfl_up_sync(0xffu, pv, o);
                if (tid >= o) { pe += te; pv += tv; }
            }
            sm.b.dwarpE[tid] = pe; sm.b.dwarpV[tid] = pv;
        }
        __syncthreads();
        if (tid < NB) {
            double offE = (wrp > 0) ? sm.b.dwarpE[wrp - 1] : 0.0;
            double offV = (wrp > 0) ? sm.b.dwarpV[wrp - 1] : 0.0;
            double inclE = ise + offE, inclV = isv + offV;
            double totalV = sm.b.dwarpV[7];
            sm.b.prefExp[tid] = (float)(inclE - se);
            sm.b.sufVal[tid]  = (float)(totalV - (inclV - sv));
            if (tid == 0) sm.b.sufVal[NB] = 0.0f;
        }
    }
    __syncthreads();

    // queries: y_atom[n,h] (2 per thread)
    for (int n = tid; n < N_MOL; n += NTHR) {
        float am  = g_amolT[h][n];
        float t   = -am;
        float eam = expf(am);
        int b  = bin_of(t, mnv, inv);
        int s0 = sm.b.binStart[b], e0 = sm.b.binStart[b + 1];
        float acc = eam * sm.b.prefExp[b] + sm.b.sufVal[b + 1]
                  + (float)(P_PRO - e0) * (am + 1.0f);
        for (int i = s0; i < e0; i++) {
            float v = sm.b.bufB[i];
            acc += (v <= t) ? eam * sm.b.bufC[i] : (am + 1.0f + v);
        }
        sm.b.bufA[n] = acc;
    }
    __syncthreads();

    // segment sum -> g_ys
    if (tid < NGRAPH) {
        int b = tid;
        int lo = 0, hi = N_MOL;
        while (lo < hi) { int m = (lo + hi) >> 1; if (sm.b.bs[m] < b) lo = m + 1; else hi = m; }
        int s = lo;
        lo = 0; hi = N_MOL;
        while (lo < hi) { int m = (lo + hi) >> 1; if (sm.b.bs[m] < b + 1) lo = m + 1; else hi = m; }
        int e = lo;
        float acc = 0.0f;
        for (int n = s; n < e; n++) acc += sm.b.bufA[n];
        g_ys[b * HEADS + h] = acc * 0.001f;
    }
    __threadfence();
    __syncthreads();
    if (blockIdx.x != 0) {
        if (tid == 0) atomicAdd(&g_done, 1);
        return;
    }

    // ============ final MLP (block 0, after all heads done) ============
    if (tid == 0) {
        while (atomicAdd(&g_done, 0) < NBLK - 1) {}
        atomicExch(&g_done, 0);
        __threadfence();
    }
    __syncthreads();
    if (tid < NGRAPH) {
        float ys[HEADS];
#pragma unroll
        for (int hh = 0; hh < HEADS; hh++)
            ys[hh] = __ldcg(&g_ys[tid * HEADS + hh]);
        float o = b2[0];
#pragma unroll
        for (int j = 0; j < 2 * HEADS; j++) {
            float a = b1[j];
#pragma unroll
            for (int hh = 0; hh < HEADS; hh++)
                a += ys[hh] * W1[hh * (2 * HEADS) + j];
            float el = (a > 0.0f) ? a : (expf(a) - 1.0f);
            o += el * W2[j];
        }
        out[tid] = o;
    }
}

// Inputs (metadata order):
// 0 mol_feats [2048,64] f32   1 fused_feats [2048,64] f32
// 2 Wmu [128,16] f32          3 bmu [16] f32
// 4 W1 [16,32] f32            5 b1 [32] f32
// 6 W2 [32,1] f32             7 b2 [1] f32
// 8 mol_batch [2048] int64-or-int32   9 num_graphs (static B=64)
extern "C" void kernel_launch(void* const* d_in, const int* in_sizes, int n_in,
                              void* d_out, int out_size) {
    fused_kernel<<<NBLK, NTHR>>>(
        (const float*)d_in[0], (const float*)d_in[1],
        (const float*)d_in[2], (const float*)d_in[3],
        (const float*)d_in[4], (const float*)d_in[5],
        (const float*)d_in[6], (const float*)d_in[7],
        (const int*)d_in[8], (float*)d_out);
}

// round 4
// speedup vs baseline: 1.5104x; 1.5104x over previous
#include <cuda_runtime.h>
#include <math.h>

#define N_MOL  2048
#define P_PRO  2048
#define HID    64
#define HEADS  16
#define NGRAPH 64
#define NB     256          // counting-sort bins (== NTHR: 1 bin per thread)
#define NBLK   128          // grid size (1 wave on 148 SMs)
#define NTHR   256

// ---- scratch (no allocation allowed) ----
__device__ float g_amolT[HEADS][N_MOL];
__device__ float g_aproT[HEADS][P_PRO];
__device__ float g_ys[NGRAPH * HEADS];
__device__ int   g_gen;     // barrier generation (monotone across replays)
__device__ int   g_count;   // barrier arrivals (self-resets)
__device__ int   g_done;    // head-blocks-finished counter (self-resets)

struct SmemB {
    float  bufA[P_PRO];      // raw a_pro -> later y_atom
    float  bufB[P_PRO];      // bin-grouped values
    float  bufC[P_PRO];      // bin-grouped exp(values)
    int    bs[N_MOL];        // batch ids
    int    hist[NB];
    int    cnt[NB];
    int    binStart[NB + 1];
    float  prefExp[NB];      // sum exp over bins < k
    float  sufVal[NB + 1];   // sum val over bins >= k
    float  redmn[8], redmx[8];
    int    iwarp[8];
    double dwarpE[8], dwarpV[8];
    float  mnv, mxv;
    int    flag;
};
struct SmemA { float rows[16][HID]; };
union SmemU { SmemA a; SmemB b; };

__device__ __forceinline__ int bin_of(float v, float mn, float inv) {
    // no-FMA-contraction form so all call sites compute identically
    int b = (int)(__fmul_rn(__fsub_rn(v, mn), inv));
    return b < 0 ? 0 : (b > NB - 1 ? NB - 1 : b);
}

__global__ __launch_bounds__(NTHR, 1)
void fused_kernel(const float* __restrict__ mol,
                  const float* __restrict__ pro,
                  const float* __restrict__ Wmu,
                  const float* __restrict__ bmu,
                  const float* __restrict__ W1,
                  const float* __restrict__ b1,
                  const float* __restrict__ W2,
                  const float* __restrict__ b2,
                  const int*   __restrict__ batch32,
                  float* __restrict__ out) {
    __shared__ SmemU sm;
    int tid  = threadIdx.x;
    int lane = tid & 31;
    int wrp  = tid >> 5;

    // ================= Phase A: projections (all 128 blocks) =================
    // block handles 32 rows (of 4096 = mol then pro), all 16 heads.
    {
        int r16 = tid >> 4;       // 0..15
        int h   = tid & 15;
        for (int half = 0; half < 2; half++) {
            int rowbase = blockIdx.x * 32 + half * 16;
            {   // cooperative load: 16 rows x 64 floats, one float4 per thread
                int lrow = tid >> 4, c4 = tid & 15;
                int grow = rowbase + lrow;
                const float* base = (grow < N_MOL) ? (mol + grow * HID)
                                                   : (pro + (grow - N_MOL) * HID);
                *(float4*)&sm.a.rows[lrow][c4 * 4] = *(const float4*)(base + c4 * 4);
            }
            __syncthreads();
            int grow = rowbase + r16;
            bool is_mol = (grow < N_MOL);
            float acc = is_mol ? bmu[h] : 0.0f;
            const float* w = is_mol ? (Wmu + h) : (Wmu + HID * HEADS + h);
#pragma unroll
            for (int k = 0; k < HID; k++)
                acc += sm.a.rows[r16][k] * w[k * HEADS];
            if (is_mol) g_amolT[h][grow] = acc;
            else        g_aproT[h][grow - N_MOL] = acc;
            __syncthreads();
        }
    }

    // ================= grid barrier (only head blocks spin) =================
    __threadfence();
    __syncthreads();
    if (tid == 0) {
        int my = *(volatile int*)&g_gen;
        if (atomicAdd(&g_count, 1) == NBLK - 1) {
            atomicExch(&g_count, 0);
            __threadfence();
            atomicAdd(&g_gen, 1);
        } else if (blockIdx.x < HEADS) {
            while (*(volatile int*)&g_gen == my) { __nanosleep(64); }
        }
        __threadfence();
    }
    __syncthreads();
    if (blockIdx.x >= HEADS) return;   // non-head blocks exit without spinning

    // ================= Phase B: per-head pipeline (blocks 0..15) =================
    int h = blockIdx.x;

    // load raw a_pro, batch ids; min/max reduce
    float mn = 1e30f, mx = -1e30f;
    for (int i = tid; i < P_PRO; i += NTHR) {
        float v = g_aproT[h][i];
        sm.b.bufA[i] = v;
        mn = fminf(mn, v); mx = fmaxf(mx, v);
    }
    for (int i = tid; i < N_MOL; i += NTHR) sm.b.bs[i] = batch32[i];
    sm.b.hist[tid] = 0;
    sm.b.cnt[tid]  = 0;
    if (tid == 0) sm.b.flag = 0;
#pragma unroll
    for (int o = 16; o > 0; o >>= 1) {
        mn = fminf(mn, __shfl_xor_sync(0xffffffffu, mn, o));
        mx = fmaxf(mx, __shfl_xor_sync(0xffffffffu, mx, o));
    }
    if (lane == 0) { sm.b.redmn[wrp] = mn; sm.b.redmx[wrp] = mx; }
    __syncthreads();
    if (tid == 0) {
        float a = sm.b.redmn[0], b = sm.b.redmx[0];
#pragma unroll
        for (int i = 1; i < NTHR / 32; i++) {
            a = fminf(a, sm.b.redmn[i]); b = fmaxf(b, sm.b.redmx[i]);
        }
        sm.b.mnv = a; sm.b.mxv = b;
    }
    // int64 detection: sorted int32 word stream is monotone; int64's is not
    for (int i = tid; i < N_MOL - 1; i += NTHR)
        if (sm.b.bs[i] > sm.b.bs[i + 1]) sm.b.flag = 1;
    __syncthreads();
    if (sm.b.flag) {  // int64: take low word of each element
        for (int i = tid; i < N_MOL; i += NTHR) sm.b.bs[i] = batch32[2 * i];
    }
    float mnv = sm.b.mnv;
    float inv = (sm.b.mxv > mnv) ? (float)NB / (sm.b.mxv - mnv) : 0.0f;

    // histogram (8 elements per thread)
    for (int i = tid; i < P_PRO; i += NTHR)
        atomicAdd(&sm.b.hist[bin_of(sm.b.bufA[i], mnv, inv)], 1);
    __syncthreads();

    // exclusive scan of hist -> binStart (warp-shfl hierarchical, 2 barriers)
    int myCnt, myIncl;
    {
        myCnt = sm.b.hist[tid];
        int s = myCnt;
#pragma unroll
        for (int o = 1; o < 32; o <<= 1) {
            int t = __shfl_up_sync(0xffffffffu, s, o);
            if (lane >= o) s += t;
        }
        if (lane == 31) sm.b.iwarp[wrp] = s;
        __syncthreads();
        if (tid < 8) {
            int p = sm.b.iwarp[tid];
#pragma unroll
            for (int o = 1; o < 8; o <<= 1) {
                int t = __shfl_up_sync(0xffu, p, o);
                if (tid >= o) p += t;
            }
            sm.b.iwarp[tid] = p;
        }
        __syncthreads();
        myIncl = s + (wrp > 0 ? sm.b.iwarp[wrp - 1] : 0);
        sm.b.binStart[tid + 1] = myIncl;
        if (tid == 0) sm.b.binStart[0] = 0;
    }
    __syncthreads();

    // scatter into bins (value + exp)
    for (int i = tid; i < P_PRO; i += NTHR) {
        float v = sm.b.bufA[i];
        int b = bin_of(v, mnv, inv);
        int pos = sm.b.binStart[b] + atomicAdd(&sm.b.cnt[b], 1);
        sm.b.bufB[pos] = v;
        sm.b.bufC[pos] = expf(v);
    }
    __syncthreads();

    // per-bin sums + joint double scan (prefExp exclusive / sufVal suffix)
    {
        int s0 = myIncl - myCnt, e0 = myIncl;   // this thread's bin extent
        float fe = 0.0f, fv = 0.0f;
        for (int i = s0; i < e0; i++) { fe += sm.b.bufC[i]; fv += sm.b.bufB[i]; }
        double se = (double)fe, sv = (double)fv;
        double ise = se, isv = sv;
#pragma unroll
        for (int o = 1; o < 32; o <<= 1) {
            double te = __shfl_up_sync(0xffffffffu, ise, o);
            double tv = __shfl_up_sync(0xffffffffu, isv, o);
            if (lane >= o) { ise += te; isv += tv; }
        }
        if (lane == 31) { sm.b.dwarpE[wrp] = ise; sm.b.dwarpV[wrp] = isv; }
        __syncthreads();
        if (tid < 8) {
            double pe = sm.b.dwarpE[tid], pv = sm.b.dwarpV[tid];
#pragma unroll
            for (int o = 1; o < 8; o <<= 1) {
                double te = __shfl_up_sync(0xffu, pe, o);
                double tv = __shfl_up_sync(0xffu, pv, o);
                if (tid >= o) { pe += te; pv += tv; }
            }
            sm.b.dwarpE[tid] = pe; sm.b.dwarpV[tid] = pv;
        }
        __syncthreads();
        double offE = (wrp > 0) ? sm.b.dwarpE[wrp - 1] : 0.0;
        double offV = (wrp > 0) ? sm.b.dwarpV[wrp - 1] : 0.0;
        double inclE = ise + offE, inclV = isv + offV;
        double totalV = sm.b.dwarpV[7];
        sm.b.prefExp[tid] = (float)(inclE - se);
        sm.b.sufVal[tid]  = (float)(totalV - (inclV - sv));
        if (tid == 0) sm.b.sufVal[NB] = 0.0f;
    }
    __syncthreads();

    // queries: y_atom[n,h] (8 per thread)
    for (int n = tid; n < N_MOL; n += NTHR) {
        float am  = g_amolT[h][n];
        float t   = -am;
        float eam = expf(am);
        int b  = bin_of(t, mnv, inv);
        int s0 = sm.b.binStart[b], e0 = sm.b.binStart[b + 1];
        float acc = eam * sm.b.prefExp[b] + sm.b.sufVal[b + 1]
                  + (float)(P_PRO - e0) * (am + 1.0f);
        for (int i = s0; i < e0; i++) {
            float v = sm.b.bufB[i];
            acc += (v <= t) ? eam * sm.b.bufC[i] : (am + 1.0f + v);
        }
        sm.b.bufA[n] = acc;   // bufA reused
    }
    __syncthreads();

    // segment sum -> g_ys
    if (tid < NGRAPH) {
        int b = tid;
        int lo = 0, hi = N_MOL;
        while (lo < hi) { int m = (lo + hi) >> 1; if (sm.b.bs[m] < b) lo = m + 1; else hi = m; }
        int s = lo;
        lo = 0; hi = N_MOL;
        while (lo < hi) { int m = (lo + hi) >> 1; if (sm.b.bs[m] < b + 1) lo = m + 1; else hi = m; }
        int e = lo;
        float acc = 0.0f;
        for (int n = s; n < e; n++) acc += sm.b.bufA[n];
        g_ys[b * HEADS + h] = acc * 0.001f;
    }
    __threadfence();
    __syncthreads();
    if (blockIdx.x != 0) {
        if (tid == 0) atomicAdd(&g_done, 1);
        return;
    }

    // ================= final MLP (block 0 after all heads done) =================
    if (tid == 0) {
        while (atomicAdd(&g_done, 0) < HEADS - 1) { __nanosleep(64); }
        atomicExch(&g_done, 0);            // reset for next replay
        __threadfence();
    }
    __syncthreads();
    if (tid < NGRAPH) {
        float ys[HEADS];
#pragma unroll
        for (int hh = 0; hh < HEADS; hh++)
            ys[hh] = __ldcg(&g_ys[tid * HEADS + hh]);  // L1-bypass
        float o = b2[0];
#pragma unroll
        for (int j = 0; j < 2 * HEADS; j++) {
            float a = b1[j];
#pragma unroll
            for (int hh = 0; hh < HEADS; hh++)
                a += ys[hh] * W1[hh * (2 * HEADS) + j];
            float el = (a > 0.0f) ? a : (expf(a) - 1.0f);
            o += el * W2[j];
        }
        out[tid] = o;
    }
}

// Inputs (metadata order):
// 0 mol_feats [2048,64] f32   1 fused_feats [2048,64] f32
// 2 Wmu [128,16] f32          3 bmu [16] f32
// 4 W1 [16,32] f32            5 b1 [32] f32
// 6 W2 [32,1] f32             7 b2 [1] f32
// 8 mol_batch [2048] int64-or-int32   9 num_graphs (static B=64)
extern "C" void kernel_launch(void* const* d_in, const int* in_sizes, int n_in,
                              void* d_out, int out_size) {
    fused_kernel<<<NBLK, NTHR>>>(
        (const float*)d_in[0], (const float*)d_in[1],
        (const float*)d_in[2], (const float*)d_in[3],
        (const float*)d_in[4], (const float*)d_in[5],
        (const float*)d_in[6], (const float*)d_in[7],
        (const int*)d_in[8], (float*)d_out);
}